// round 9
// baseline (speedup 1.0000x reference)
#include <cuda_runtime.h>
#include <math.h>

#define H 1024
#define V 50257
#define L 40

// ---- scratch (__device__ globals: allocation-free) ----
__device__ float g_xa[2 * H];        // [x ; attn_applied]
__device__ float g_attn_logit[L];
__device__ float g_g[H];             // relu(comb)
__device__ float g_gi[3 * H];
__device__ float g_gh[3 * H];
__device__ float g_hnew[H];
__device__ float g_pm[1184];         // per-block partial max
__device__ float g_ps[1184];         // per-block partial sumexp
__device__ unsigned g_cnt_attn = 0;  // last-block counters (reset by consumer)
__device__ unsigned g_cnt_gru  = 0;

__device__ __forceinline__ float warp_sum(float v) {
    #pragma unroll
    for (int o = 16; o; o >>= 1) v += __shfl_xor_sync(0xffffffffu, v, o);
    return v;
}

// ---------------------------------------------------------------------------
// Kernel A (fused): attention logits in parallel (40 blocks) + embedding copy
// (block 40) + last-block epilogue (softmax over 40, attn_applied, outputs).
// 41 blocks x 256.
// ---------------------------------------------------------------------------
__global__ __launch_bounds__(256)
void k_attn(const int* __restrict__ input,
            const float* __restrict__ hidden,
            const float* __restrict__ enc,
            const float* __restrict__ emb,
            const float* __restrict__ W_attn,
            const float* __restrict__ b_attn,
            float* __restrict__ out) {
    __shared__ float red[8];
    __shared__ float sh_w[L];
    __shared__ bool  is_last;
    const int tid = threadIdx.x;
    const int bid = blockIdx.x;
    const int row_idx = input[0];
    const float* xrow = emb + (size_t)row_idx * H;

    if (bid == L) {
        // copy x into g_xa[0..H)
        const float4* x4 = (const float4*)xrow;
        float4* d4 = (float4*)g_xa;
        d4[tid] = x4[tid];   // 256 float4 = 1024 floats
    } else {
        // logit for row bid: dot(W_attn[bid], [x ; h]) over 2048
        const float4* wr = (const float4*)(W_attn + (size_t)bid * 2 * H);
        const float4* x4 = (const float4*)xrow;
        const float4* h4 = (const float4*)hidden;
        float acc = 0.f;
        #pragma unroll
        for (int j = 0; j < 2; j++) {
            int k = tid + j * 256;            // 0..511
            float4 a = wr[k];
            float4 b = (k < 256) ? x4[k] : h4[k - 256];
            acc += a.x * b.x + a.y * b.y + a.z * b.z + a.w * b.w;
        }
        acc = warp_sum(acc);
        if ((tid & 31) == 0) red[tid >> 5] = acc;
        __syncthreads();
        if (tid < 8) {
            float v = red[tid];
            #pragma unroll
            for (int o = 4; o; o >>= 1) v += __shfl_xor_sync(0xffu, v, o);
            if (tid == 0) g_attn_logit[bid] = v + b_attn[bid];
        }
    }

    // last-block epilogue
    __threadfence();
    if (tid == 0) {
        unsigned t = atomicAdd(&g_cnt_attn, 1u);
        is_last = (t == L);                    // 41 blocks -> last sees 40
    }
    __syncthreads();
    if (!is_last) return;
    __threadfence();

    if (tid == 0) {
        float m = g_attn_logit[0];
        for (int l = 1; l < L; l++) m = fmaxf(m, g_attn_logit[l]);
        float s = 0.f;
        for (int l = 0; l < L; l++) { float e = __expf(g_attn_logit[l] - m); sh_w[l] = e; s += e; }
        float inv = 1.f / s;
        for (int l = 0; l < L; l++) sh_w[l] *= inv;
        g_cnt_attn = 0;                        // reset for next graph replay
    }
    __syncthreads();

    if (tid < L) out[V + H + tid] = sh_w[tid];

    // attn_applied: 256 threads x 4 cols
    #pragma unroll
    for (int j = 0; j < 4; j++) {
        int col = tid + j * 256;
        float acc = 0.f;
        #pragma unroll 8
        for (int l = 0; l < L; l++) acc += sh_w[l] * enc[l * H + col];
        g_xa[H + col] = acc;
    }
}

// ---------------------------------------------------------------------------
// Kernel B: g = relu(W_comb @ [x; attn_applied] + b_comb). 128 blocks x 256,
// warp-per-row (8 rows/block), operand staged in SMEM.
// ---------------------------------------------------------------------------
__global__ __launch_bounds__(256, 8)
void k_comb(const float* __restrict__ W_comb,
            const float* __restrict__ b_comb) {
    __shared__ float4 sh[2 * H / 4];
    const int tid = threadIdx.x;
    for (int k = tid; k < 2 * H / 4; k += 256) sh[k] = ((const float4*)g_xa)[k];
    __syncthreads();
    const int warp = tid >> 5, lane = tid & 31;
    const int row = blockIdx.x * 8 + warp;   // exactly 1024 rows
    const float4* wr = (const float4*)(W_comb + (size_t)row * 2 * H);
    float acc = 0.f;
    #pragma unroll 4
    for (int k = lane; k < 2 * H / 4; k += 32) {
        float4 a = wr[k], b = sh[k];
        acc += a.x * b.x + a.y * b.y + a.z * b.z + a.w * b.w;
    }
    acc = warp_sum(acc);
    if (lane == 0) g_g[row] = fmaxf(acc + b_comb[row], 0.f);
}

// ---------------------------------------------------------------------------
// Kernel C (fused): gi/gh matvecs (384 blocks x 256, warp-per-row) + last-block
// GRU gate epilogue -> g_hnew and out[V..V+H).
// ---------------------------------------------------------------------------
__global__ __launch_bounds__(256, 8)
void k_gru_mm(const float* __restrict__ W_ih,
              const float* __restrict__ b_ih,
              const float* __restrict__ W_hh,
              const float* __restrict__ b_hh,
              const float* __restrict__ hidden,
              float* __restrict__ out) {
    __shared__ float4 shg[H / 4];
    __shared__ float4 shh[H / 4];
    __shared__ bool   is_last;
    const int tid = threadIdx.x;
    for (int k = tid; k < H / 4; k += 256) {
        shg[k] = ((const float4*)g_g)[k];
        shh[k] = ((const float4*)hidden)[k];
    }
    __syncthreads();
    const int warp = tid >> 5, lane = tid & 31;
    const int row = blockIdx.x * 8 + warp;   // exactly 3072 rows
    const float4* wi = (const float4*)(W_ih + (size_t)row * H);
    const float4* wh = (const float4*)(W_hh + (size_t)row * H);
    float ai = 0.f, ah = 0.f;
    #pragma unroll 4
    for (int k = lane; k < H / 4; k += 32) {
        float4 a = wi[k], b = shg[k];
        ai += a.x * b.x + a.y * b.y + a.z * b.z + a.w * b.w;
        float4 c = wh[k], d = shh[k];
        ah += c.x * d.x + c.y * d.y + c.z * d.z + c.w * d.w;
    }
    ai = warp_sum(ai);
    ah = warp_sum(ah);
    if (lane == 0) {
        g_gi[row] = ai + b_ih[row];
        g_gh[row] = ah + b_hh[row];
    }

    // last-block gate epilogue
    __threadfence();
    if (tid == 0) {
        unsigned t = atomicAdd(&g_cnt_gru, 1u);
        is_last = (t == 383u);
    }
    __syncthreads();
    if (!is_last) return;
    __threadfence();
    if (tid == 0) g_cnt_gru = 0;             // reset for next replay

    #pragma unroll
    for (int j = 0; j < 4; j++) {
        int i = tid + j * 256;               // 0..1023
        float r = 1.f / (1.f + __expf(-(g_gi[i] + g_gh[i])));
        float z = 1.f / (1.f + __expf(-(g_gi[H + i] + g_gh[H + i])));
        float n = tanhf(g_gi[2 * H + i] + r * g_gh[2 * H + i]);
        float hn = (1.f - z) * n + z * hidden[i];
        g_hnew[i] = hn;
        out[V + i] = hn;
    }
}

// ---------------------------------------------------------------------------
// Kernel E (dominant, ~206 MB): logits = W_out @ h_new + b_out, stored to
// out[0..V), fused per-block online (max, sumexp) partials.
// 1184 blocks x 256 threads; warp computes TWO rows per iteration.
// ---------------------------------------------------------------------------
#define LOGIT_BLOCKS 1184
__global__ __launch_bounds__(256)
void k_logits(const float* __restrict__ W_out,
              const float* __restrict__ b_out,
              float* __restrict__ out) {
    __shared__ float4 shh[H / 4];
    __shared__ float sm[8], ss[8];
    const int tid = threadIdx.x;
    for (int k = tid; k < H / 4; k += 256) shh[k] = ((const float4*)g_hnew)[k];
    __syncthreads();
    const int warp = tid >> 5, lane = tid & 31;
    float m = -1e30f, s = 0.f;
    for (int base = blockIdx.x * 16; base < V; base += LOGIT_BLOCKS * 16) {
        const int row0 = base + warp * 2;
        const int row1 = row0 + 1;
        float acc0 = 0.f, acc1 = 0.f;
        if (row0 < V) {
            const float4* wr0 = (const float4*)(W_out + (size_t)row0 * H);
            if (row1 < V) {
                const float4* wr1 = (const float4*)(W_out + (size_t)row1 * H);
                #pragma unroll 8
                for (int k = lane; k < H / 4; k += 32) {
                    float4 b = shh[k];
                    float4 a0 = wr0[k];
                    float4 a1 = wr1[k];
                    acc0 += a0.x * b.x + a0.y * b.y + a0.z * b.z + a0.w * b.w;
                    acc1 += a1.x * b.x + a1.y * b.y + a1.z * b.z + a1.w * b.w;
                }
            } else {
                #pragma unroll 8
                for (int k = lane; k < H / 4; k += 32) {
                    float4 b = shh[k];
                    float4 a0 = wr0[k];
                    acc0 += a0.x * b.x + a0.y * b.y + a0.z * b.z + a0.w * b.w;
                }
            }
        }
        acc0 = warp_sum(acc0);
        acc1 = warp_sum(acc1);
        if (lane == 0 && row0 < V) {
            float l0 = acc0 + b_out[row0];
            out[row0] = l0;
            float mn = fmaxf(m, l0);
            s = s * __expf(m - mn) + __expf(l0 - mn);
            m = mn;
            if (row1 < V) {
                float l1 = acc1 + b_out[row1];
                out[row1] = l1;
                mn = fmaxf(m, l1);
                s = s * __expf(m - mn) + __expf(l1 - mn);
                m = mn;
            }
        }
    }
    if (lane == 0) { sm[warp] = m; ss[warp] = s; }
    __syncthreads();
    if (tid == 0) {
        float M = sm[0], S = ss[0];
        #pragma unroll
        for (int w = 1; w < 8; w++) {
            float mn = fmaxf(M, sm[w]);
            S = S * __expf(M - mn) + ss[w] * __expf(sm[w] - mn);
            M = mn;
        }
        g_pm[blockIdx.x] = M;
        g_ps[blockIdx.x] = S;
    }
}

// ---------------------------------------------------------------------------
// Kernel G (fused): every block redundantly reduces the 1184 (m,s) partials
// (fixed order -> bit-identical logZ in all blocks), then subtracts.
// 100 blocks x 256.
// ---------------------------------------------------------------------------
__global__ __launch_bounds__(256)
void k_finish(float* __restrict__ out) {
    __shared__ float sm[8], ss[8];
    const int tid = threadIdx.x;
    // per-thread fixed-order partial reduce over 1184 entries
    float m = -1e30f, s = 0.f;
    for (int i = tid; i < LOGIT_BLOCKS; i += 256) {
        float m2 = g_pm[i], s2 = g_ps[i];
        float mn = fmaxf(m, m2);
        s = s * __expf(m - mn) + s2 * __expf(m2 - mn);
        m = mn;
    }
    #pragma unroll
    for (int o = 16; o; o >>= 1) {
        float m2 = __shfl_xor_sync(0xffffffffu, m, o);
        float s2 = __shfl_xor_sync(0xffffffffu, s, o);
        float mn = fmaxf(m, m2);
        s = s * __expf(m - mn) + s2 * __expf(m2 - mn);
        m = mn;
    }
    if ((tid & 31) == 0) { sm[tid >> 5] = m; ss[tid >> 5] = s; }
    __syncthreads();
    float M = sm[0], S = ss[0];
    #pragma unroll
    for (int w = 1; w < 8; w++) {
        float mn = fmaxf(M, sm[w]);
        S = S * __expf(M - mn) + ss[w] * __expf(sm[w] - mn);
        M = mn;
    }
    const float lz = M + logf(S);

    const int n4 = V / 4;                 // 12564 float4s
    float4* o4 = (float4*)out;
    for (int i = blockIdx.x * blockDim.x + tid; i < n4;
         i += gridDim.x * blockDim.x) {
        float4 v = o4[i];
        v.x -= lz; v.y -= lz; v.z -= lz; v.w -= lz;
        o4[i] = v;
    }
    if (blockIdx.x == 0 && tid == 0) out[V - 1] -= lz;  // remainder
}

// ---------------------------------------------------------------------------
extern "C" void kernel_launch(void* const* d_in, const int* in_sizes, int n_in,
                              void* d_out, int out_size) {
    const int*   input  = (const int*)  d_in[0];
    const float* hidden = (const float*)d_in[1];
    const float* enc    = (const float*)d_in[2];
    const float* emb    = (const float*)d_in[3];
    const float* W_attn = (const float*)d_in[4];
    const float* b_attn = (const float*)d_in[5];
    const float* W_comb = (const float*)d_in[6];
    const float* b_comb = (const float*)d_in[7];
    const float* W_ih   = (const float*)d_in[8];
    const float* b_ih   = (const float*)d_in[9];
    const float* W_hh   = (const float*)d_in[10];
    const float* b_hh   = (const float*)d_in[11];
    const float* W_out  = (const float*)d_in[12];
    const float* b_out  = (const float*)d_in[13];
    float* out = (float*)d_out;

    k_attn  <<<L + 1, 256>>>(input, hidden, enc, emb, W_attn, b_attn, out);
    k_comb  <<<128, 256>>>(W_comb, b_comb);
    k_gru_mm<<<384, 256>>>(W_ih, b_ih, W_hh, b_hh, hidden, out);
    k_logits<<<LOGIT_BLOCKS, 256>>>(W_out, b_out, out);
    k_finish<<<100, 256>>>(out);
}

// round 12
// speedup vs baseline: 1.0917x; 1.0917x over previous
#include <cuda_runtime.h>
#include <math.h>

#define H 1024
#define V 50257
#define L 40
#define NB 592            // 4 blocks/SM x 148 SMs (also resident on 152-SM GB300)

// ---- scratch (__device__ globals: allocation-free) ----
__device__ float g_xa[2 * H];        // [x ; attn_applied]
__device__ float g_attn_logit[L];
__device__ float g_g[H];             // relu(comb)
__device__ float g_gi[3 * H];
__device__ float g_gh[3 * H];
__device__ float g_hnew[H];
__device__ float g_pm[NB];           // per-block partial max
__device__ float g_ps[NB];           // per-block partial sumexp
__device__ unsigned g_bar_count = 0; // grid barrier arrivals (self-resetting)
__device__ unsigned g_bar_sense = 0; // monotone epoch (wrap-safe compares)

__device__ __forceinline__ float warp_sum(float v) {
    #pragma unroll
    for (int o = 16; o; o >>= 1) v += __shfl_xor_sync(0xffffffffu, v, o);
    return v;
}

// Grid-wide barrier: all NB blocks are co-resident by occupancy construction.
__device__ __forceinline__ void grid_bar(unsigned target) {
    __syncthreads();
    if (threadIdx.x == 0) {
        __threadfence();                      // publish this block's writes
        unsigned t = atomicAdd(&g_bar_count, 1u);
        if (t == NB - 1u) {
            g_bar_count = 0u;                 // reset before release
            __threadfence();
            atomicAdd(&g_bar_sense, 1u);      // release
        } else {
            while ((int)(*(volatile unsigned*)&g_bar_sense - target) < 0) {}
        }
        __threadfence();                      // acquire
    }
    __syncthreads();
}

// Fire-and-forget L2 prefetch of a 128B line (no correctness surface).
__device__ __forceinline__ void l2_prefetch(const void* p) {
    asm volatile("prefetch.global.L2 [%0];" :: "l"(p));
}

__global__ __launch_bounds__(256, 4)
void k_fused(const int* __restrict__ input,
             const float* __restrict__ hidden,
             const float* __restrict__ enc,
             const float* __restrict__ emb,
             const float* __restrict__ W_attn,
             const float* __restrict__ b_attn,
             const float* __restrict__ W_comb,
             const float* __restrict__ b_comb,
             const float* __restrict__ W_ih,
             const float* __restrict__ b_ih,
             const float* __restrict__ W_hh,
             const float* __restrict__ b_hh,
             const float* __restrict__ W_out,
             const float* __restrict__ b_out,
             float* __restrict__ out) {
    __shared__ float4 sbuf4[512];             // 8 KB staging, reused per phase
    __shared__ float  red[8];
    __shared__ float  shw[L];
    __shared__ float  sm[8], ss[8];
    __shared__ unsigned s_base;

    const int tid  = threadIdx.x;
    const int bid  = blockIdx.x;
    const int warp = tid >> 5, lane = tid & 31;

    if (tid == 0) s_base = *(volatile unsigned*)&g_bar_sense;  // stable at launch
    __syncthreads();
    const unsigned base = s_base;

    const int row_idx = input[0];
    const float* xrow = emb + (size_t)row_idx * H;

    // ---- P1: attention logits (blocks 0..39) + embedding copy (block 40) ----
    if (bid < L) {
        const float4* wr = (const float4*)(W_attn + (size_t)bid * 2 * H);
        const float4* x4 = (const float4*)xrow;
        const float4* h4 = (const float4*)hidden;
        float acc = 0.f;
        #pragma unroll
        for (int j = 0; j < 2; j++) {
            int k = tid + j * 256;            // 0..511
            float4 a = wr[k];
            float4 b = (k < 256) ? x4[k] : h4[k - 256];
            acc += a.x * b.x + a.y * b.y + a.z * b.z + a.w * b.w;
        }
        acc = warp_sum(acc);
        if (lane == 0) red[warp] = acc;
        __syncthreads();
        if (tid < 8) {
            float v = red[tid];
            #pragma unroll
            for (int o = 4; o; o >>= 1) v += __shfl_xor_sync(0xffu, v, o);
            if (tid == 0) g_attn_logit[bid] = v + b_attn[bid];
        }
    } else if (bid == L) {
        ((float4*)g_xa)[tid] = ((const float4*)xrow)[tid];   // x -> g_xa[0..H)
    }
    grid_bar(base + 1);

    // ---- P2: softmax (redundant in blocks 0..3) + attn_applied slices ----
    if (bid < 4) {
        if (tid == 0) {
            float m = g_attn_logit[0];
            for (int l = 1; l < L; l++) m = fmaxf(m, g_attn_logit[l]);
            float s = 0.f;
            for (int l = 0; l < L; l++) { float e = __expf(g_attn_logit[l] - m); shw[l] = e; s += e; }
            float inv = 1.f / s;
            for (int l = 0; l < L; l++) shw[l] *= inv;
        }
        __syncthreads();
        if (bid == 0 && tid < L) out[V + H + tid] = shw[tid];
        int col = bid * 256 + tid;            // 0..1023
        float acc = 0.f;
        #pragma unroll 8
        for (int l = 0; l < L; l++) acc += shw[l] * enc[l * H + col];
        g_xa[H + col] = acc;
    }
    grid_bar(base + 2);

    // ---- P3: g = relu(W_comb @ xa + b_comb)  (blocks 0..127, warp/row) ----
    // Idle blocks (128..591) prefetch W_out rows 0..9471 (P6 iteration 0,
    // 38.8 MB) into L2.
    if (bid < 128) {
        for (int k = tid; k < 2 * H / 4; k += 256) sbuf4[k] = ((const float4*)g_xa)[k];
        __syncthreads();
        const int row = bid * 8 + warp;       // 1024 rows
        const float4* wr = (const float4*)(W_comb + (size_t)row * 2 * H);
        float acc = 0.f;
        #pragma unroll 4
        for (int k = lane; k < 2 * H / 4; k += 32) {
            float4 a = wr[k], b = sbuf4[k];
            acc += a.x * b.x + a.y * b.y + a.z * b.z + a.w * b.w;
        }
        acc = warp_sum(acc);
        if (lane == 0) g_g[row] = fmaxf(acc + b_comb[row], 0.f);
    } else {
        const char* wp = (const char*)W_out;
        const size_t lines = (size_t)9472 * 32;              // 128B lines
        for (size_t i = (size_t)(bid - 128) * 256 + tid; i < lines;
             i += (size_t)(NB - 128) * 256)
            l2_prefetch(wp + i * 128);
    }
    grid_bar(base + 3);

    // ---- P4: gi/gh matvecs (blocks 0..383, warp/row does both dots) ----
    // Idle blocks (384..591) prefetch W_out rows 9472..18943 (P6 iter 1).
    if (bid < 384) {
        for (int k = tid; k < H / 4; k += 256) {
            sbuf4[k]       = ((const float4*)g_g)[k];
            sbuf4[256 + k] = ((const float4*)hidden)[k];
        }
        __syncthreads();
        const int row = bid * 8 + warp;       // 3072 rows
        const float4* wi = (const float4*)(W_ih + (size_t)row * H);
        const float4* wh = (const float4*)(W_hh + (size_t)row * H);
        float ai = 0.f, ah = 0.f;
        #pragma unroll 4
        for (int k = lane; k < H / 4; k += 32) {
            float4 a = wi[k], b = sbuf4[k];
            ai += a.x * b.x + a.y * b.y + a.z * b.z + a.w * b.w;
            float4 c = wh[k], d = sbuf4[256 + k];
            ah += c.x * d.x + c.y * d.y + c.z * d.z + c.w * d.w;
        }
        ai = warp_sum(ai);
        ah = warp_sum(ah);
        if (lane == 0) {
            g_gi[row] = ai + b_ih[row];
            g_gh[row] = ah + b_hh[row];
        }
    } else {
        const char* wp = (const char*)W_out + (size_t)9472 * 4096;
        const size_t lines = (size_t)9472 * 32;
        for (size_t i = (size_t)(bid - 384) * 256 + tid; i < lines;
             i += (size_t)(NB - 384) * 256)
            l2_prefetch(wp + i * 128);
    }
    grid_bar(base + 4);

    // ---- P5: GRU gate (blocks 0..3) -> g_hnew, out[V..V+H) ----
    if (bid < 4) {
        int i = bid * 256 + tid;              // 0..1023
        float r = 1.f / (1.f + __expf(-(g_gi[i] + g_gh[i])));
        float z = 1.f / (1.f + __expf(-(g_gi[H + i] + g_gh[H + i])));
        float n = tanhf(g_gi[2 * H + i] + r * g_gh[2 * H + i]);
        float hn = (1.f - z) * n + z * hidden[i];
        g_hnew[i] = hn;
        out[V + i] = hn;
    }
    grid_bar(base + 5);

    // ---- P6: logits (all blocks; 2 rows/warp; online max/sumexp partials) ----
    {
        for (int k = tid; k < H / 4; k += 256) sbuf4[k] = ((const float4*)g_hnew)[k];
        __syncthreads();
        float m = -1e30f, s = 0.f;
        for (int bse = bid * 16; bse < V; bse += NB * 16) {
            const int row0 = bse + warp * 2;
            const int row1 = row0 + 1;
            float acc0 = 0.f, acc1 = 0.f;
            if (row0 < V) {
                const float4* wr0 = (const float4*)(W_out + (size_t)row0 * H);
                if (row1 < V) {
                    const float4* wr1 = (const float4*)(W_out + (size_t)row1 * H);
                    #pragma unroll 8
                    for (int k = lane; k < H / 4; k += 32) {
                        float4 b = sbuf4[k];
                        float4 a0 = wr0[k];
                        float4 a1 = wr1[k];
                        acc0 += a0.x * b.x + a0.y * b.y + a0.z * b.z + a0.w * b.w;
                        acc1 += a1.x * b.x + a1.y * b.y + a1.z * b.z + a1.w * b.w;
                    }
                } else {
                    #pragma unroll 8
                    for (int k = lane; k < H / 4; k += 32) {
                        float4 b = sbuf4[k];
                        float4 a0 = wr0[k];
                        acc0 += a0.x * b.x + a0.y * b.y + a0.z * b.z + a0.w * b.w;
                    }
                }
            }
            acc0 = warp_sum(acc0);
            acc1 = warp_sum(acc1);
            if (lane == 0 && row0 < V) {
                float l0 = acc0 + b_out[row0];
                out[row0] = l0;
                float mn = fmaxf(m, l0);
                s = s * __expf(m - mn) + __expf(l0 - mn);
                m = mn;
                if (row1 < V) {
                    float l1 = acc1 + b_out[row1];
                    out[row1] = l1;
                    mn = fmaxf(m, l1);
                    s = s * __expf(m - mn) + __expf(l1 - mn);
                    m = mn;
                }
            }
        }
        if (lane == 0) { sm[warp] = m; ss[warp] = s; }
        __syncthreads();
        if (tid == 0) {
            float M = sm[0], S = ss[0];
            #pragma unroll
            for (int w = 1; w < 8; w++) {
                float mn = fmaxf(M, sm[w]);
                S = S * __expf(M - mn) + ss[w] * __expf(sm[w] - mn);
                M = mn;
            }
            g_pm[bid] = M;
            g_ps[bid] = S;
        }
    }
    grid_bar(base + 6);

    // ---- P7: redundant fixed-order logZ reduce (bit-identical) + subtract ----
    {
        float m = -1e30f, s = 0.f;
        for (int i = tid; i < NB; i += 256) {
            float m2 = g_pm[i], s2 = g_ps[i];
            float mn = fmaxf(m, m2);
            s = s * __expf(m - mn) + s2 * __expf(m2 - mn);
            m = mn;
        }
        #pragma unroll
        for (int o = 16; o; o >>= 1) {
            float m2 = __shfl_xor_sync(0xffffffffu, m, o);
            float s2 = __shfl_xor_sync(0xffffffffu, s, o);
            float mn = fmaxf(m, m2);
            s = s * __expf(m - mn) + s2 * __expf(m2 - mn);
            m = mn;
        }
        if (lane == 0) { sm[warp] = m; ss[warp] = s; }
        __syncthreads();
        float M = sm[0], S = ss[0];
        #pragma unroll
        for (int w = 1; w < 8; w++) {
            float mn = fmaxf(M, sm[w]);
            S = S * __expf(M - mn) + ss[w] * __expf(sm[w] - mn);
            M = mn;
        }
        const float lz = M + logf(S);

        const int n4 = V / 4;                 // 12564 float4s
        float4* o4 = (float4*)out;
        for (int i = bid * 256 + tid; i < n4; i += NB * 256) {
            float4 v = o4[i];
            v.x -= lz; v.y -= lz; v.z -= lz; v.w -= lz;
            o4[i] = v;
        }
        if (bid == 0 && tid == 0) out[V - 1] -= lz;  // remainder element
    }
}

// ---------------------------------------------------------------------------
extern "C" void kernel_launch(void* const* d_in, const int* in_sizes, int n_in,
                              void* d_out, int out_size) {
    const int*   input  = (const int*)  d_in[0];
    const float* hidden = (const float*)d_in[1];
    const float* enc    = (const float*)d_in[2];
    const float* emb    = (const float*)d_in[3];
    const float* W_attn = (const float*)d_in[4];
    const float* b_attn = (const float*)d_in[5];
    const float* W_comb = (const float*)d_in[6];
    const float* b_comb = (const float*)d_in[7];
    const float* W_ih   = (const float*)d_in[8];
    const float* b_ih   = (const float*)d_in[9];
    const float* W_hh   = (const float*)d_in[10];
    const float* b_hh   = (const float*)d_in[11];
    const float* W_out  = (const float*)d_in[12];
    const float* b_out  = (const float*)d_in[13];
    float* out = (float*)d_out;

    k_fused<<<NB, 256>>>(input, hidden, enc, emb, W_attn, b_attn,
                         W_comb, b_comb, W_ih, b_ih, W_hh, b_hh,
                         W_out, b_out, out);
}